// round 10
// baseline (speedup 1.0000x reference)
#include <cuda_runtime.h>
#include <cstdint>

#define TT 8192
#define DD 2048

typedef unsigned long long ull;

// ---------------- device scratch (no allocations allowed) ----------------
__device__ float g_pre[(size_t)TT * DD];        // 64 MB: pre = x @ W1^T + b1
__device__ float g_hs[(size_t)(TT + 1) * DD];   // 64 MB: h per step; sign bit = not-ready

// ---------------- packed f32x2 helpers ----------------
__device__ __forceinline__ ull pk(float lo, float hi) {
    ull r;
    asm("mov.b64 %0, {%1, %2};" : "=l"(r) : "f"(lo), "f"(hi));
    return r;
}
__device__ __forceinline__ void upk(ull v, float& lo, float& hi) {
    asm("mov.b64 {%0, %1}, %2;" : "=f"(lo), "=f"(hi) : "l"(v));
}
__device__ __forceinline__ void fma2(ull& d, ull a, ull b) {
    asm("fma.rn.f32x2 %0, %1, %2, %0;" : "+l"(d) : "l"(a), "l"(b));
}

// ---------------- volatile ld/st (morally strong, guaranteed fresh+live) ----------
__device__ __forceinline__ uint4 ldvol_v4(const float* p) {
    uint4 v;
    asm volatile("ld.volatile.global.v4.u32 {%0,%1,%2,%3}, [%4];"
                 : "=r"(v.x), "=r"(v.y), "=r"(v.z), "=r"(v.w) : "l"(p));
    return v;
}
__device__ __forceinline__ void stvol_f32(float* p, float v) {
    asm volatile("st.volatile.global.f32 [%0], %1;" :: "l"(p), "f"(v));
}

// ---------------- poison kernel: set sign bits (= not ready) everywhere ----------
__global__ void poison_kernel() {
    uint4 p = make_uint4(0xFFFFFFFFu, 0xFFFFFFFFu, 0xFFFFFFFFu, 0xFFFFFFFFu);
    size_t n = (size_t)(TT + 1) * DD / 4;
    uint4* dst = (uint4*)g_hs;
    for (size_t i = (size_t)blockIdx.x * blockDim.x + threadIdx.x; i < n;
         i += (size_t)gridDim.x * blockDim.x)
        dst[i] = p;
}

// ---------------- GEMM: g_pre[t][n] = sum_k x[t][k] * W1[n][k] + b1[n] ----------------
#define BM 128
#define BN 128
#define BK 16
#define LDP 132

__global__ __launch_bounds__(256, 2) void gemm_kernel(
    const float* __restrict__ A,      // x  (TT x DD)
    const float* __restrict__ B,      // W1 (DD x DD), computing A @ B^T
    const float* __restrict__ bias)   // b1
{
    __shared__ __align__(16) float As[BK][LDP];
    __shared__ __align__(16) float Bs[BK][LDP];

    const int tid = threadIdx.x;
    const int m0 = blockIdx.y * BM;
    const int n0 = blockIdx.x * BN;
    const int tx = tid & 15;
    const int ty = tid >> 4;

    ull acc[8][4];
#pragma unroll
    for (int r = 0; r < 8; r++)
#pragma unroll
        for (int c = 0; c < 4; c++) acc[r][c] = 0ull;

    for (int k0 = 0; k0 < DD; k0 += BK) {
#pragma unroll
        for (int i = 0; i < 2; i++) {
            int id = tid + i * 256;
            int r = id >> 2;
            int c = (id & 3) * 4;
            float4 va = *(const float4*)(A + (size_t)(m0 + r) * DD + k0 + c);
            As[c + 0][r] = va.x; As[c + 1][r] = va.y;
            As[c + 2][r] = va.z; As[c + 3][r] = va.w;
            float4 vb = *(const float4*)(B + (size_t)(n0 + r) * DD + k0 + c);
            Bs[c + 0][r] = vb.x; Bs[c + 1][r] = vb.y;
            Bs[c + 2][r] = vb.z; Bs[c + 3][r] = vb.w;
        }
        __syncthreads();

#pragma unroll
        for (int k = 0; k < BK; k++) {
            float4 a0 = *(const float4*)&As[k][ty * 8];
            float4 a1 = *(const float4*)&As[k][ty * 8 + 4];
            ulonglong2 bq0 = *(const ulonglong2*)&Bs[k][tx * 8];
            ulonglong2 bq1 = *(const ulonglong2*)&Bs[k][tx * 8 + 4];
            ull bp0 = bq0.x, bp1 = bq0.y, bp2 = bq1.x, bp3 = bq1.y;
            float ar[8] = {a0.x, a0.y, a0.z, a0.w, a1.x, a1.y, a1.z, a1.w};
#pragma unroll
            for (int r = 0; r < 8; r++) {
                ull ad = pk(ar[r], ar[r]);
                fma2(acc[r][0], ad, bp0);
                fma2(acc[r][1], ad, bp1);
                fma2(acc[r][2], ad, bp2);
                fma2(acc[r][3], ad, bp3);
            }
        }
        __syncthreads();
    }

#pragma unroll
    for (int c = 0; c < 4; c++) {
        int n = n0 + tx * 8 + c * 2;
        float blo = bias[n], bhi = bias[n + 1];
#pragma unroll
        for (int r = 0; r < 8; r++) {
            float lo, hi;
            upk(acc[r][c], lo, hi);
            int m = m0 + ty * 8 + r;
            *(float2*)(g_pre + (size_t)m * DD + n) = make_float2(lo + blo, hi + bhi);
        }
    }
}

// ---------------- persistent scan kernel (sign-bit dataflow sync) ------------------
#define NCTA 128
#define NTH  512
#define ROWS 16   // DD / NCTA rows per CTA; warp w owns row blk*16+w
// thread t owns k-chunk [4t, 4t+4)

__global__ __launch_bounds__(NTH, 1) void scan_kernel(
    const float* __restrict__ h0,
    const float* __restrict__ W2,
    const float* __restrict__ b2)
{
    // cross-warp combine buffer: [2 buffers][row*17 + warp], conflict-free
    __shared__ float s2[2][ROWS * 17];

    const int tid  = threadIdx.x;
    const int blk  = blockIdx.x;
    const int lane = tid & 31;
    const int wid  = tid >> 5;
    const int k0   = tid * 4;
    // butterfly output mapping: lane l ends holding row bitrev4(l & 15)
    const int rrow = ((lane & 1) << 3) | ((lane & 2) << 1) |
                     ((lane & 4) >> 1) | ((lane & 8) >> 3);

    // register-resident W2 slab: rows [blk*16, blk*16+16), cols [k0, k0+4)
    ull w2r0[ROWS], w2r1[ROWS];
#pragma unroll
    for (int j = 0; j < ROWS; j++) {
        float4 w = *(const float4*)(W2 + (size_t)(blk * ROWS + j) * DD + k0);
        w2r0[j] = pk(w.x, w.y);
        w2r1[j] = pk(w.z, w.w);
    }
    const int myrow = blk * ROWS + wid;
    const float myb2 = b2[myrow];
    float pre_next = __ldg(&g_pre[myrow]);

    for (int t = 0; t < TT; t++) {
        float h0v, h1v, h2v, h3v;
        if (t == 0) {
            // h0 is kernel input: ready by definition (and may be negative)
            float4 hv = *(const float4*)(h0 + k0);
            h0v = hv.x; h1v = hv.y; h2v = hv.z; h3v = hv.w;
        } else {
            // one 16B volatile poll; sign bits are the ready flags
            const float* src = g_hs + (size_t)t * DD + k0;
            uint4 a = ldvol_v4(src);
            while (((a.x | a.y | a.z | a.w) & 0x80000000u) != 0u) {
                __nanosleep(40);
                a = ldvol_v4(src);
            }
            h0v = __uint_as_float(a.x);
            h1v = __uint_as_float(a.y);
            h2v = __uint_as_float(a.z);
            h3v = __uint_as_float(a.w);
        }

        float pre_cur = pre_next;
        if (t + 1 < TT) pre_next = __ldg(&g_pre[(size_t)(t + 1) * DD + myrow]);

        // ---- per-thread partials for all 16 CTA rows (packed f32x2 MACs) ----
        ull h01 = pk(h0v, h1v);
        ull h23 = pk(h2v, h3v);
        float p[ROWS];
#pragma unroll
        for (int j = 0; j < ROWS; j++) {
            ull acc = 0ull;
            fma2(acc, w2r0[j], h01);
            fma2(acc, w2r1[j], h23);
            float lo, hi;
            upk(acc, lo, hi);
            p[j] = lo + hi;
        }

        // ---- warp butterfly: 16 values x 32 lanes -> row bitrev4(lane) per lane ----
#pragma unroll
        for (int width = 8; width >= 1; width >>= 1) {
            const unsigned m = 16 / (unsigned)width;   // 2,4,8... no: see below
            // stage mask: width 8 -> xor 1, width 4 -> xor 2, width 2 -> xor 4, width 1 -> xor 8
            const unsigned xm = 8u / (unsigned)width;  // 1,2,4,8
#pragma unroll
            for (int i = 0; i < width; i++) {
                float send = (lane & xm) ? p[i] : p[i + width];
                float keep = (lane & xm) ? p[i + width] : p[i];
                p[i] = keep + __shfl_xor_sync(0xffffffffu, send, xm);
            }
            (void)m;
        }
        p[0] += __shfl_xor_sync(0xffffffffu, p[0], 16);

        // ---- cross-warp combine: 16 warps x 16 rows through 1KB smem ----
        float* buf = s2[t & 1];
        if (lane < 16) buf[rrow * 17 + wid] = p[0];
        __syncthreads();

        float v = (lane < 16) ? buf[wid * 17 + lane] : 0.f;
        v += __shfl_xor_sync(0xffffffffu, v, 8);
        v += __shfl_xor_sync(0xffffffffu, v, 4);
        v += __shfl_xor_sync(0xffffffffu, v, 2);
        v += __shfl_xor_sync(0xffffffffu, v, 1);

        if (lane == 0) {
            float y = fmaxf(v + pre_cur + myb2, 0.f);
            // clear sign bit: no-op on ReLU output, and it IS the ready tag
            y = __uint_as_float(__float_as_uint(y) & 0x7FFFFFFFu);
            stvol_f32(&g_hs[(size_t)(t + 1) * DD + myrow], y);
        }
        // no trailing barrier: s2 is double-buffered and a warp must pass the
        // next step's __syncthreads before touching this buffer again.
    }
}

// ---------------- final tiny matvec: out[j] = h . Wf[j] + bf[j] ----------------
__global__ void final_kernel(const float* __restrict__ Wf,
                             const float* __restrict__ bf,
                             float* __restrict__ out)
{
    const int wid = threadIdx.x >> 5;   // 4 warps, one per output row
    const int lane = threadIdx.x & 31;
    const float* h = g_hs + (size_t)TT * DD;
    const float* w = Wf + (size_t)wid * DD;
    float s = 0.f;
#pragma unroll
    for (int i = 0; i < 16; i++) {
        int k = i * 128 + lane * 4;
        float4 hv = *(const float4*)(h + k);
        float4 wv = *(const float4*)(w + k);
        s += hv.x * wv.x + hv.y * wv.y + hv.z * wv.z + hv.w * wv.w;
    }
    for (int off = 16; off; off >>= 1) s += __shfl_xor_sync(0xffffffffu, s, off);
    if (lane == 0) out[wid] = s + bf[wid];
}

// ---------------- launch ----------------
extern "C" void kernel_launch(void* const* d_in, const int* in_sizes, int n_in,
                              void* d_out, int out_size)
{
    const float* x  = (const float*)d_in[0];
    const float* h0 = (const float*)d_in[1];
    const float* W1 = (const float*)d_in[2];
    const float* b1 = (const float*)d_in[3];
    const float* W2 = (const float*)d_in[4];
    const float* b2 = (const float*)d_in[5];
    const float* Wf = (const float*)d_in[6];
    const float* bf = (const float*)d_in[7];
    float* out = (float*)d_out;

    poison_kernel<<<2048, 256>>>();
    gemm_kernel<<<dim3(DD / BN, TT / BM), 256>>>(x, W1, b1);
    scan_kernel<<<NCTA, NTH>>>(h0, W2, b2);
    final_kernel<<<1, 128>>>(Wf, bf, out);
}